// round 1
// baseline (speedup 1.0000x reference)
#include <cuda_runtime.h>
#include <math.h>

// ---------------- problem constants ----------------
#define T_DIM 64
#define B_DIM 32
#define C_DIM 256
#define V_DIM 25
#define H_DIM 8
#define HD_DIM 32
#define TBSZ   (T_DIM * B_DIM)            // 2048
#define PLANE  (B_DIM * C_DIM * V_DIM)    // 204800
#define TOT    (T_DIM * PLANE)            // 13107200

// ---------------- device scratch (no mallocs allowed) ----------------
__device__ float g_buf0[TOT];   // qkv_in, later attn
__device__ float g_yq[TOT];     // q bn-conv output, later proj bn-conv output
__device__ float g_yk[TOT];     // k bn-conv output
__device__ float g_yv[TOT];     // v bn-conv output
__device__ float g_qs[TOT];     // q spikes
__device__ float g_kvl[TOT];    // kv_local = k_s * v_s

__device__ float g_wt[4][C_DIM * C_DIM];   // transposed weights: [mat][c][o]
__device__ float g_scale[4][C_DIM];        // fused BN scale
__device__ float g_shift[4][C_DIM];        // fused BN shift (proj includes bias)
__device__ float g_topo[H_DIM][V_DIM * V_DIM];
__device__ float g_decay[C_DIM];           // per (h,d)

// ---------------- f32x2 packed FMA helpers (Blackwell) ----------------
__device__ __forceinline__ unsigned long long bcast2(float x) {
    unsigned long long r;
    asm("mov.b64 %0, {%1, %1};" : "=l"(r) : "f"(x));
    return r;
}
__device__ __forceinline__ void fma2(unsigned long long& d, unsigned long long a, unsigned long long b) {
    asm("fma.rn.f32x2 %0, %1, %2, %0;" : "+l"(d) : "l"(a), "l"(b));
}
__device__ __forceinline__ float2 unpack2(unsigned long long v) {
    float2 r;
    asm("mov.b64 {%0, %1}, %2;" : "=f"(r.x), "=f"(r.y) : "l"(v));
    return r;
}

// ---------------- K0: prep (transpose weights, BN consts, topo softmax, decay) ----------------
struct PrepArgs {
    const float* w[4];       // q,k,v,proj weights (O x C row-major)
    const float* gamma[4];
    const float* beta[4];
    const float* mean[4];
    const float* var[4];
    const float* projb;
    const float* base;       // (V,V)
    const float* learned;    // (1,H,V,V)
    const float* sdw;        // (1,1,H,1,HD)
};

__global__ void k_prep(PrepArgs p) {
    int blk = blockIdx.x, tid = threadIdx.x;
    if (blk < 4) {
        const float* w = p.w[blk];
        float* wt = g_wt[blk];
        for (int idx = tid; idx < C_DIM * C_DIM; idx += 256) {
            int o = idx >> 8, c = idx & 255;
            wt[c * C_DIM + o] = w[idx];
        }
        float sc = p.gamma[blk][tid] * rsqrtf(p.var[blk][tid] + 1e-5f);
        float sh = p.beta[blk][tid] - p.mean[blk][tid] * sc;
        if (blk == 3) sh += p.projb[tid] * sc;
        g_scale[blk][tid] = sc;
        g_shift[blk][tid] = sh;
    } else if (blk == 4) {
        // topo softmax: topo[h][i][j] = softmax_j(base[i][j] + 0.5*learned[h][i][j])
        if (tid < H_DIM * V_DIM) {
            int h = tid / V_DIM, i = tid - h * V_DIM;
            float l[V_DIM];
            float mx = -1e30f;
            for (int j = 0; j < V_DIM; j++) {
                l[j] = p.base[i * V_DIM + j] + 0.5f * p.learned[(h * V_DIM + i) * V_DIM + j];
                mx = fmaxf(mx, l[j]);
            }
            float sum = 0.f;
            for (int j = 0; j < V_DIM; j++) { l[j] = expf(l[j] - mx); sum += l[j]; }
            float inv = 1.f / sum;
            for (int j = 0; j < V_DIM; j++) g_topo[h][i * V_DIM + j] = l[j] * inv;
        }
    } else {
        // decay = clip(sigmoid(sdw), 0.01, 0.99), index h*HD + d
        float w = p.sdw[tid];
        float sg = 1.f / (1.f + expf(-w));
        g_decay[tid] = fminf(0.99f, fmaxf(0.01f, sg));
    }
}

// ---------------- K1: qkv_in = a*|dx| + (1-a)*x ----------------
__global__ void k_qkvin(const float* __restrict__ x, const float* __restrict__ alpha) {
    int idx = blockIdx.x * 256 + threadIdx.x;
    if (idx >= TOT) return;
    int t = idx / PLANE;
    int r = idx - t * PLANE;
    int c = (r / V_DIM) & (C_DIM - 1);
    float xv = x[idx];
    float g = (t == 0) ? 0.f : fabsf(xv - x[idx - PLANE]);
    float a = alpha[c];
    g_buf0[idx] = a * g + (1.f - a) * xv;
}

// ---------------- K2/K5: GEMM (256x256 @ 256x25 per tb-column) + fused BN ----------------
// One block per (tb, matrix). 128 threads, each owns 2 output rows x 26 packed lanes.
#define KC 32
#define VP 28
__global__ void __launch_bounds__(128) k_gemm(const float* __restrict__ xin, int pass) {
    int m;
    const float* in;
    float* out;
    if (pass == 0) {
        m = blockIdx.y;
        in = (m == 2) ? xin : g_buf0;           // q,k read qkv_in; v reads x
        out = (m == 0) ? g_yq : (m == 1) ? g_yk : g_yv;
    } else {
        m = 3;
        in = g_buf0;                             // attn
        out = g_yq;                              // proj bn-conv output
    }
    int tb = blockIdx.x;
    int tid = threadIdx.x;
    const float* xcol = in + (size_t)tb * (C_DIM * V_DIM);
    const float* w = g_wt[m];

    __shared__ __align__(16) float s[2][KC][VP];
    if (tid < 2 * KC) {
        int bb = tid / KC, c = tid - bb * KC;
        s[bb][c][25] = 0.f; s[bb][c][26] = 0.f; s[bb][c][27] = 0.f;
    }

    unsigned long long acc[2][13];
#pragma unroll
    for (int i = 0; i < 2; i++)
#pragma unroll
        for (int j = 0; j < 13; j++) acc[i][j] = 0ULL;

    // preload chunk 0
    for (int i = tid; i < KC * V_DIM; i += 128) {
        int c = i / V_DIM, v = i - c * V_DIM;
        s[0][c][v] = xcol[i];
    }

    int o0 = tid * 2;
    for (int k0 = 0; k0 < C_DIM; k0 += KC) {
        __syncthreads();
        int buf = (k0 / KC) & 1;
        if (k0 + KC < C_DIM) {
            const float* src = xcol + (k0 + KC) * V_DIM;
            for (int i = tid; i < KC * V_DIM; i += 128) {
                int c = i / V_DIM, v = i - c * V_DIM;
                s[buf ^ 1][c][v] = src[i];
            }
        }
#pragma unroll 4
        for (int c = 0; c < KC; c++) {
            float2 w2 = *reinterpret_cast<const float2*>(w + (k0 + c) * C_DIM + o0);
            unsigned long long wa = bcast2(w2.x);
            unsigned long long wb = bcast2(w2.y);
            const unsigned long long* s2 = reinterpret_cast<const unsigned long long*>(&s[buf][c][0]);
#pragma unroll
            for (int j = 0; j < 13; j++) {
                unsigned long long sv = s2[j];
                fma2(acc[0][j], wa, sv);
                fma2(acc[1][j], wb, sv);
            }
        }
    }

    // epilogue: fused BN  y = acc*scale + shift
#pragma unroll
    for (int i = 0; i < 2; i++) {
        int o = o0 + i;
        float sc = g_scale[m][o], sh = g_shift[m][o];
        float* dst = out + (size_t)tb * (C_DIM * V_DIM) + o * V_DIM;
#pragma unroll
        for (int j = 0; j < 13; j++) {
            float2 f = unpack2(acc[i][j]);
            int v = 2 * j;
            dst[v] = f.x * sc + sh;
            if (v + 1 < V_DIM) dst[v + 1] = f.y * sc + sh;
        }
    }
}

// ---------------- K3: triple LIF (v_th = 1) + kv_local ----------------
__global__ void k_lif3() {
    int idx = blockIdx.x * 256 + threadIdx.x;
    if (idx >= PLANE) return;
    float vq = 0.f, vk = 0.f, vv = 0.f;
    for (int t = 0; t < T_DIM; t++) {
        int off = t * PLANE + idx;
        float aq = g_yq[off];
        vq = vq + (aq - vq) * 0.5f;
        float sq = (vq >= 1.f) ? 1.f : 0.f;
        vq *= (1.f - sq);
        float ak = g_yk[off];
        vk = vk + (ak - vk) * 0.5f;
        float sk = (vk >= 1.f) ? 1.f : 0.f;
        vk *= (1.f - sk);
        float av = g_yv[off];
        vv = vv + (av - vv) * 0.5f;
        float sv = (vv >= 1.f) ? 1.f : 0.f;
        vv *= (1.f - sv);
        g_qs[off] = sq;
        g_kvl[off] = sk * sv;
    }
}

// ---------------- K4: topo routing + LIF(0.5) + SSRE -> attn ----------------
// block = (b, h, d-octet): 8 d x 25 i = 200 active threads of 224.
__global__ void __launch_bounds__(224) k_topo_ssre() {
    int bid = blockIdx.x;
    int b = bid >> 5;
    int rest = bid & 31;
    int h = rest >> 2;
    int dg = rest & 3;
    int tid = threadIdx.x;

    __shared__ float topo_s[V_DIM * V_DIM];
    __shared__ float kvb[2][200];
    for (int i = tid; i < V_DIM * V_DIM; i += 224) topo_s[i] = g_topo[h][i];

    bool active = tid < 200;
    int d_local = tid / V_DIM;
    int i = tid - d_local * V_DIM;
    int d = dg * 8 + d_local;
    int base = b * (C_DIM * V_DIM) + (h * HD_DIM + dg * 8) * V_DIM; // (b, c0, 0)

    float dec = 0.f;
    if (active) dec = g_decay[h * HD_DIM + d];
    float omd = 1.f - dec;
    float vm = 0.f, S = 0.f;

    if (active) kvb[0][tid] = g_kvl[base + tid];

    for (int t = 0; t < T_DIM; t++) {
        __syncthreads();
        int cur = t & 1;
        if (t + 1 < T_DIM && active) kvb[cur ^ 1][tid] = g_kvl[(t + 1) * PLANE + base + tid];
        if (active) {
            const float* kr = &kvb[cur][d_local * V_DIM];
            const float* tr = &topo_s[i * V_DIM];
            float sp = 0.f, sp2 = 0.f;
#pragma unroll
            for (int j = 0; j < 24; j += 2) {
                sp += tr[j] * kr[j];
                sp2 += tr[j + 1] * kr[j + 1];
            }
            sp += tr[24] * kr[24] + sp2;
            // LIF v_th = 0.5
            vm = vm + (sp - vm) * 0.5f;
            float sk = (vm >= 0.5f) ? 1.f : 0.f;
            vm *= (1.f - sk);
            // SSRE
            S = dec * S + omd * sk;
            int off = t * PLANE + base + tid;
            g_buf0[off] = g_qs[off] * S;   // attn = q * S
        }
    }
}

// ---------------- K6: final LIF(0.5) + identity ----------------
__global__ void k_final(const float* __restrict__ x, float* __restrict__ out) {
    int idx = blockIdx.x * 256 + threadIdx.x;
    if (idx >= PLANE) return;
    float vm = 0.f;
    for (int t = 0; t < T_DIM; t++) {
        int off = t * PLANE + idx;
        float y = g_yq[off];  // proj bn-conv output
        vm = vm + (y - vm) * 0.5f;
        float s = (vm >= 0.5f) ? 1.f : 0.f;
        vm *= (1.f - s);
        out[off] = s + x[off];
    }
}

// ---------------- launch ----------------
extern "C" void kernel_launch(void* const* d_in, const int* in_sizes, int n_in,
                              void* d_out, int out_size) {
    const float* x = (const float*)d_in[0];
    const float* alpha = (const float*)d_in[1];

    PrepArgs p;
    p.w[0] = (const float*)d_in[2];
    p.w[1] = (const float*)d_in[3];
    p.w[2] = (const float*)d_in[4];

    if (in_sizes[5] == 625) {
        // setup_inputs() dict order
        p.base    = (const float*)d_in[5];
        p.learned = (const float*)d_in[6];
        p.sdw     = (const float*)d_in[7];
        p.w[3]    = (const float*)d_in[8];
        p.projb   = (const float*)d_in[9];
        for (int m = 0; m < 4; m++) {
            int o = 10 + m * 4;
            p.gamma[m] = (const float*)d_in[o + 0];
            p.beta[m]  = (const float*)d_in[o + 1];
            p.mean[m]  = (const float*)d_in[o + 2];
            p.var[m]   = (const float*)d_in[o + 3];
        }
    } else {
        // reference() signature order
        for (int m = 0; m < 3; m++) {
            int o = 5 + m * 4;
            p.gamma[m] = (const float*)d_in[o + 0];
            p.beta[m]  = (const float*)d_in[o + 1];
            p.mean[m]  = (const float*)d_in[o + 2];
            p.var[m]   = (const float*)d_in[o + 3];
        }
        p.base    = (const float*)d_in[17];
        p.learned = (const float*)d_in[18];
        p.sdw     = (const float*)d_in[19];
        p.w[3]    = (const float*)d_in[20];
        p.projb   = (const float*)d_in[21];
        p.gamma[3] = (const float*)d_in[22];
        p.beta[3]  = (const float*)d_in[23];
        p.mean[3]  = (const float*)d_in[24];
        p.var[3]   = (const float*)d_in[25];
    }

    float* out = (float*)d_out;

    k_prep<<<6, 256>>>(p);
    k_qkvin<<<(TOT + 255) / 256, 256>>>(x, alpha);
    k_gemm<<<dim3(TBSZ, 3), 128>>>(x, 0);            // q,k,v conv + BN
    k_lif3<<<(PLANE + 255) / 256, 256>>>();
    k_topo_ssre<<<B_DIM * H_DIM * 4, 224>>>();
    k_gemm<<<dim3(TBSZ, 1), 128>>>(x, 1);            // proj conv + BN(+bias)
    k_final<<<(PLANE + 255) / 256, 256>>>(x, out);
}

// round 2
// speedup vs baseline: 1.0360x; 1.0360x over previous
#include <cuda_runtime.h>
#include <math.h>

typedef unsigned long long ull;

// ---------------- problem constants ----------------
#define T_DIM 64
#define B_DIM 32
#define C_DIM 256
#define V_DIM 25
#define H_DIM 8
#define HD_DIM 32
#define TBSZ   (T_DIM * B_DIM)            // 2048
#define PLANE  (B_DIM * C_DIM * V_DIM)    // 204800
#define TOT    (T_DIM * PLANE)            // 13107200

// ---------------- device scratch ----------------
__device__ __align__(16) float g_buf0[TOT];   // qkv_in, later attn
__device__ __align__(16) float g_yq[TOT];     // q bn-conv out, later proj bn-conv out
__device__ __align__(16) float g_yk[TOT];
__device__ __align__(16) float g_yv[TOT];
__device__ __align__(16) float g_qs[TOT];     // q spikes
__device__ __align__(16) float g_kvl[TOT];    // k_s * v_s

__device__ __align__(16) float g_wt[4][C_DIM * C_DIM];  // [mat][c][o] (transposed)
__device__ float g_scale[4][C_DIM];
__device__ float g_shift[4][C_DIM];
__device__ float g_topo[H_DIM][V_DIM * V_DIM];
__device__ float g_decay[C_DIM];

// ---------------- f32x2 helpers ----------------
__device__ __forceinline__ ull bcast2(float x) {
    ull r;
    asm("mov.b64 %0, {%1, %1};" : "=l"(r) : "f"(x));
    return r;
}
__device__ __forceinline__ void fma2(ull& d, ull a, ull b) {
    asm("fma.rn.f32x2 %0, %1, %2, %0;" : "+l"(d) : "l"(a), "l"(b));
}
__device__ __forceinline__ float2 unpack2(ull v) {
    float2 r;
    asm("mov.b64 {%0, %1}, %2;" : "=f"(r.x), "=f"(r.y) : "l"(v));
    return r;
}

// ---------------- K0: prep ----------------
struct PrepArgs {
    const float* w[4];
    const float* gamma[4];
    const float* beta[4];
    const float* mean[4];
    const float* var[4];
    const float* projb;
    const float* base;
    const float* learned;
    const float* sdw;
};

__global__ void k_prep(PrepArgs p) {
    int blk = blockIdx.x, tid = threadIdx.x;
    if (blk < 4) {
        const float* w = p.w[blk];
        float* wt = g_wt[blk];
        for (int idx = tid; idx < C_DIM * C_DIM; idx += 256) {
            int o = idx >> 8, c = idx & 255;
            wt[c * C_DIM + o] = w[idx];
        }
        float sc = p.gamma[blk][tid] * rsqrtf(p.var[blk][tid] + 1e-5f);
        float sh = p.beta[blk][tid] - p.mean[blk][tid] * sc;
        if (blk == 3) sh += p.projb[tid] * sc;
        g_scale[blk][tid] = sc;
        g_shift[blk][tid] = sh;
    } else if (blk == 4) {
        if (tid < H_DIM * V_DIM) {
            int h = tid / V_DIM, i = tid - h * V_DIM;
            float l[V_DIM];
            float mx = -1e30f;
            for (int j = 0; j < V_DIM; j++) {
                l[j] = p.base[i * V_DIM + j] + 0.5f * p.learned[(h * V_DIM + i) * V_DIM + j];
                mx = fmaxf(mx, l[j]);
            }
            float sum = 0.f;
            for (int j = 0; j < V_DIM; j++) { l[j] = expf(l[j] - mx); sum += l[j]; }
            float inv = 1.f / sum;
            for (int j = 0; j < V_DIM; j++) g_topo[h][i * V_DIM + j] = l[j] * inv;
        }
    } else {
        float w = p.sdw[tid];
        float sg = 1.f / (1.f + expf(-w));
        g_decay[tid] = fminf(0.99f, fmaxf(0.01f, sg));
    }
}

// ---------------- K1: qkv_in = a*|dx| + (1-a)*x  (float4) ----------------
__global__ void k_qkvin(const float* __restrict__ x, const float* __restrict__ alpha) {
    int i4 = blockIdx.x * 256 + threadIdx.x;
    if (i4 >= TOT / 4) return;
    int idx = i4 * 4;
    int t = idx / PLANE;
    int r = idx - t * PLANE;
    float4 xv = *reinterpret_cast<const float4*>(x + idx);
    float4 xp = make_float4(0.f, 0.f, 0.f, 0.f);
    if (t > 0) xp = *reinterpret_cast<const float4*>(x + idx - PLANE);
    float o[4];
    float xa[4] = {xv.x, xv.y, xv.z, xv.w};
    float pa[4] = {xp.x, xp.y, xp.z, xp.w};
#pragma unroll
    for (int i = 0; i < 4; i++) {
        int c = ((r + i) / V_DIM) & (C_DIM - 1);
        float g = (t == 0) ? 0.f : fabsf(xa[i] - pa[i]);
        float a = alpha[c];
        o[i] = a * g + (1.f - a) * xa[i];
    }
    *reinterpret_cast<float4*>(g_buf0 + idx) = make_float4(o[0], o[1], o[2], o[3]);
}

// ---------------- K2/K5: GEMM + fused BN ----------------
// Block = (tb-pair, matrix). 128 threads: half = tid>>6 picks tb column,
// each thread computes 4 output rows x 25 V (13 f32x2 lanes).
// Weights staged in smem, double-buffered, KC=8.
#define KC 8
#define VP 28
__global__ void __launch_bounds__(128) k_gemm(const float* __restrict__ xin, int pass) {
    int m;
    const float* in;
    float* out;
    if (pass == 0) {
        m = blockIdx.y;
        in = (m == 2) ? xin : g_buf0;
        out = (m == 0) ? g_yq : (m == 1) ? g_yk : g_yv;
    } else {
        m = 3;
        in = g_buf0;
        out = g_yq;
    }
    int tb2 = blockIdx.x;            // tb pair
    int tid = threadIdx.x;
    int half = tid >> 6;
    int t6 = tid & 63;
    const float* xcol0 = in + (size_t)(2 * tb2) * (C_DIM * V_DIM);
    const float* w = g_wt[m];

    __shared__ __align__(16) float ws[2][KC][C_DIM];          // 16 KB
    __shared__ __align__(16) float xs[2][2][KC][VP];          // 3.5 KB

    // zero padding lanes (persist; loads only touch v<25)
    for (int i = tid; i < 2 * 2 * KC; i += 128) {
        int bb = i >> 4, rest = i & 15;
        int col = rest >> 3, c = rest & 7;
        xs[bb][col][c][25] = 0.f; xs[bb][col][c][26] = 0.f; xs[bb][col][c][27] = 0.f;
    }

    ull acc[4][13];
#pragma unroll
    for (int i = 0; i < 4; i++)
#pragma unroll
        for (int j = 0; j < 13; j++) acc[i][j] = 0ULL;

    // preload chunk 0
    {
        const float4* wsrc = reinterpret_cast<const float4*>(w);
        float4* wdst = reinterpret_cast<float4*>(&ws[0][0][0]);
#pragma unroll
        for (int i = tid; i < KC * C_DIM / 4; i += 128) wdst[i] = wsrc[i];
        for (int i = tid; i < 2 * KC * V_DIM; i += 128) {
            int col = i / (KC * V_DIM), r = i - col * (KC * V_DIM);
            int c = r / V_DIM, v = r - c * V_DIM;
            xs[0][col][c][v] = xcol0[col * (C_DIM * V_DIM) + c * V_DIM + v];
        }
    }

    int o0 = t6 * 4;
    for (int k0 = 0; k0 < C_DIM; k0 += KC) {
        __syncthreads();
        int buf = (k0 / KC) & 1;
        if (k0 + KC < C_DIM) {
            const float4* wsrc = reinterpret_cast<const float4*>(w + (k0 + KC) * C_DIM);
            float4* wdst = reinterpret_cast<float4*>(&ws[buf ^ 1][0][0]);
#pragma unroll
            for (int i = tid; i < KC * C_DIM / 4; i += 128) wdst[i] = wsrc[i];
            const float* xsrc = xcol0 + (k0 + KC) * V_DIM;
            for (int i = tid; i < 2 * KC * V_DIM; i += 128) {
                int col = i / (KC * V_DIM), r = i - col * (KC * V_DIM);
                int c = r / V_DIM, v = r - c * V_DIM;
                xs[buf ^ 1][col][c][v] = xsrc[col * (C_DIM * V_DIM) + c * V_DIM + v];
            }
        }
#pragma unroll
        for (int c = 0; c < KC; c++) {
            float4 w4 = *reinterpret_cast<const float4*>(&ws[buf][c][o0]);
            ull wa = bcast2(w4.x), wb = bcast2(w4.y);
            ull wcc = bcast2(w4.z), wd = bcast2(w4.w);
            const ull* s2 = reinterpret_cast<const ull*>(&xs[buf][half][c][0]);
#pragma unroll
            for (int j = 0; j < 13; j++) {
                ull sv = s2[j];
                fma2(acc[0][j], wa, sv);
                fma2(acc[1][j], wb, sv);
                fma2(acc[2][j], wcc, sv);
                fma2(acc[3][j], wd, sv);
            }
        }
    }

    // epilogue: fused BN
#pragma unroll
    for (int i = 0; i < 4; i++) {
        int o = o0 + i;
        float sc = g_scale[m][o], sh = g_shift[m][o];
        float* dst = out + (size_t)(2 * tb2 + half) * (C_DIM * V_DIM) + o * V_DIM;
#pragma unroll
        for (int j = 0; j < 13; j++) {
            float2 f = unpack2(acc[i][j]);
            int v = 2 * j;
            dst[v] = f.x * sc + sh;
            if (v + 1 < V_DIM) dst[v + 1] = f.y * sc + sh;
        }
    }
}

// ---------------- K3: triple LIF + kv_local (float4) ----------------
__global__ void k_lif3() {
    int i4 = blockIdx.x * 256 + threadIdx.x;
    if (i4 >= PLANE / 4) return;
    int idx = i4 * 4;
    float4 vq = make_float4(0, 0, 0, 0), vk = vq, vv = vq;
    for (int t = 0; t < T_DIM; t++) {
        int off = t * PLANE + idx;
        float4 aq = *reinterpret_cast<const float4*>(g_yq + off);
        float4 ak = *reinterpret_cast<const float4*>(g_yk + off);
        float4 av = *reinterpret_cast<const float4*>(g_yv + off);
        float4 sq, skv;
        float* vqp = &vq.x; float* vkp = &vk.x; float* vvp = &vv.x;
        float* aqp = &aq.x; float* akp = &ak.x; float* avp = &av.x;
        float* sqp = &sq.x; float* skvp = &skv.x;
#pragma unroll
        for (int i = 0; i < 4; i++) {
            float q = vqp[i] + (aqp[i] - vqp[i]) * 0.5f;
            float s = (q >= 1.f) ? 1.f : 0.f;
            vqp[i] = q * (1.f - s);
            sqp[i] = s;
            float k = vkp[i] + (akp[i] - vkp[i]) * 0.5f;
            float sk = (k >= 1.f) ? 1.f : 0.f;
            vkp[i] = k * (1.f - sk);
            float v = vvp[i] + (avp[i] - vvp[i]) * 0.5f;
            float sv = (v >= 1.f) ? 1.f : 0.f;
            vvp[i] = v * (1.f - sv);
            skvp[i] = sk * sv;
        }
        *reinterpret_cast<float4*>(g_qs + off) = sq;
        *reinterpret_cast<float4*>(g_kvl + off) = skv;
    }
}

// ---------------- K4: topo routing + LIF(0.5) + SSRE ----------------
__global__ void __launch_bounds__(224) k_topo_ssre() {
    int bid = blockIdx.x;
    int b = bid >> 5;
    int rest = bid & 31;
    int h = rest >> 2;
    int dg = rest & 3;
    int tid = threadIdx.x;

    __shared__ float topo_s[V_DIM * V_DIM];
    __shared__ float kvb[2][200];
    for (int i = tid; i < V_DIM * V_DIM; i += 224) topo_s[i] = g_topo[h][i];

    bool active = tid < 200;
    int d_local = tid / V_DIM;
    int i = tid - d_local * V_DIM;
    int d = dg * 8 + d_local;
    int base = b * (C_DIM * V_DIM) + (h * HD_DIM + dg * 8) * V_DIM;

    float dec = 0.f;
    if (active) dec = g_decay[h * HD_DIM + d];
    float omd = 1.f - dec;
    float vm = 0.f, S = 0.f;

    if (active) kvb[0][tid] = g_kvl[base + tid];

    for (int t = 0; t < T_DIM; t++) {
        __syncthreads();
        int cur = t & 1;
        if (t + 1 < T_DIM && active) kvb[cur ^ 1][tid] = g_kvl[(t + 1) * PLANE + base + tid];
        if (active) {
            const float* kr = &kvb[cur][d_local * V_DIM];
            const float* tr = &topo_s[i * V_DIM];
            float sp = 0.f, sp2 = 0.f;
#pragma unroll
            for (int j = 0; j < 24; j += 2) {
                sp += tr[j] * kr[j];
                sp2 += tr[j + 1] * kr[j + 1];
            }
            sp += tr[24] * kr[24] + sp2;
            vm = vm + (sp - vm) * 0.5f;
            float sk = (vm >= 0.5f) ? 1.f : 0.f;
            vm *= (1.f - sk);
            S = dec * S + omd * sk;
            int off = t * PLANE + base + tid;
            g_buf0[off] = g_qs[off] * S;
        }
    }
}

// ---------------- K6: final LIF(0.5) + identity (float4) ----------------
__global__ void k_final(const float* __restrict__ x, float* __restrict__ out) {
    int i4 = blockIdx.x * 256 + threadIdx.x;
    if (i4 >= PLANE / 4) return;
    int idx = i4 * 4;
    float4 vm = make_float4(0, 0, 0, 0);
    for (int t = 0; t < T_DIM; t++) {
        int off = t * PLANE + idx;
        float4 y = *reinterpret_cast<const float4*>(g_yq + off);
        float4 xi = *reinterpret_cast<const float4*>(x + off);
        float4 o;
        float* vp = &vm.x; float* yp = &y.x; float* xp = &xi.x; float* op = &o.x;
#pragma unroll
        for (int i = 0; i < 4; i++) {
            float v = vp[i] + (yp[i] - vp[i]) * 0.5f;
            float s = (v >= 0.5f) ? 1.f : 0.f;
            vp[i] = v * (1.f - s);
            op[i] = s + xp[i];
        }
        *reinterpret_cast<float4*>(out + off) = o;
    }
}

// ---------------- launch ----------------
extern "C" void kernel_launch(void* const* d_in, const int* in_sizes, int n_in,
                              void* d_out, int out_size) {
    const float* x = (const float*)d_in[0];
    const float* alpha = (const float*)d_in[1];

    PrepArgs p;
    p.w[0] = (const float*)d_in[2];
    p.w[1] = (const float*)d_in[3];
    p.w[2] = (const float*)d_in[4];

    if (in_sizes[5] == 625) {
        p.base    = (const float*)d_in[5];
        p.learned = (const float*)d_in[6];
        p.sdw     = (const float*)d_in[7];
        p.w[3]    = (const float*)d_in[8];
        p.projb   = (const float*)d_in[9];
        for (int m = 0; m < 4; m++) {
            int o = 10 + m * 4;
            p.gamma[m] = (const float*)d_in[o + 0];
            p.beta[m]  = (const float*)d_in[o + 1];
            p.mean[m]  = (const float*)d_in[o + 2];
            p.var[m]   = (const float*)d_in[o + 3];
        }
    } else {
        for (int m = 0; m < 3; m++) {
            int o = 5 + m * 4;
            p.gamma[m] = (const float*)d_in[o + 0];
            p.beta[m]  = (const float*)d_in[o + 1];
            p.mean[m]  = (const float*)d_in[o + 2];
            p.var[m]   = (const float*)d_in[o + 3];
        }
        p.base    = (const float*)d_in[17];
        p.learned = (const float*)d_in[18];
        p.sdw     = (const float*)d_in[19];
        p.w[3]    = (const float*)d_in[20];
        p.projb   = (const float*)d_in[21];
        p.gamma[3] = (const float*)d_in[22];
        p.beta[3]  = (const float*)d_in[23];
        p.mean[3]  = (const float*)d_in[24];
        p.var[3]   = (const float*)d_in[25];
    }

    float* out = (float*)d_out;

    k_prep<<<6, 256>>>(p);
    k_qkvin<<<(TOT / 4 + 255) / 256, 256>>>(x, alpha);
    k_gemm<<<dim3(TBSZ / 2, 3), 128>>>(x, 0);
    k_lif3<<<(PLANE / 4 + 255) / 256, 256>>>();
    k_topo_ssre<<<B_DIM * H_DIM * 4, 224>>>();
    k_gemm<<<dim3(TBSZ / 2, 1), 128>>>(x, 1);
    k_final<<<(PLANE / 4 + 255) / 256, 256>>>(x, out);
}

// round 4
// speedup vs baseline: 1.2555x; 1.2119x over previous
#include <cuda_runtime.h>
#include <math.h>

typedef unsigned long long ull;

// ---------------- problem constants ----------------
#define T_DIM 64
#define B_DIM 32
#define C_DIM 256
#define V_DIM 25
#define H_DIM 8
#define HD_DIM 32
#define PLANE  (B_DIM * C_DIM * V_DIM)    // 204800
#define TOT    (T_DIM * PLANE)            // 13107200
#define NF     (T_DIM * B_DIM * V_DIM)    // 51200  (GEMM N)

// ---------------- device scratch ----------------
// layout for GEMM-adjacent tensors: [c][t][b][v]  (addr = c*NF + t*800 + b*25 + v)
__device__ __align__(16) float g_xt[TOT];    // x transposed
__device__ __align__(16) float g_qt[TOT];    // qkv_in transposed; later attn
__device__ __align__(16) float g_yq[TOT];    // q bn-conv out; later proj bn-conv out
__device__ __align__(16) float g_yk[TOT];
__device__ __align__(16) float g_yv[TOT];
__device__ __align__(16) float g_qs[TOT];    // q spikes
__device__ __align__(16) float g_kvl[TOT];   // k_s * v_s

__device__ __align__(16) float g_wt[4][C_DIM * C_DIM];  // [mat][k][m] (transposed weights)
__device__ float g_scale[4][C_DIM];
__device__ float g_shift[4][C_DIM];
__device__ float g_topo[H_DIM][V_DIM * V_DIM];
__device__ float g_decay[C_DIM];

// ---------------- f32x2 helpers ----------------
__device__ __forceinline__ void fma2(ull& d, ull a, ull b) {
    asm("fma.rn.f32x2 %0, %1, %2, %0;" : "+l"(d) : "l"(a), "l"(b));
}
__device__ __forceinline__ float2 unpack2(ull v) {
    float2 r;
    asm("mov.b64 {%0, %1}, %2;" : "=f"(r.x), "=f"(r.y) : "l"(v));
    return r;
}

// ---------------- K0: prep ----------------
struct PrepArgs {
    const float* w[4];
    const float* gamma[4];
    const float* beta[4];
    const float* mean[4];
    const float* var[4];
    const float* projb;
    const float* base;
    const float* learned;
    const float* sdw;
};

__global__ void k_prep(PrepArgs p) {
    int blk = blockIdx.x, tid = threadIdx.x;
    if (blk < 4) {
        const float* w = p.w[blk];
        float* wt = g_wt[blk];
        for (int idx = tid; idx < C_DIM * C_DIM; idx += 256) {
            int o = idx >> 8, c = idx & 255;
            wt[c * C_DIM + o] = w[idx];
        }
        float sc = p.gamma[blk][tid] * rsqrtf(p.var[blk][tid] + 1e-5f);
        float sh = p.beta[blk][tid] - p.mean[blk][tid] * sc;
        if (blk == 3) sh += p.projb[tid] * sc;
        g_scale[blk][tid] = sc;
        g_shift[blk][tid] = sh;
    } else if (blk == 4) {
        if (tid < H_DIM * V_DIM) {
            int h = tid / V_DIM, i = tid - h * V_DIM;
            float l[V_DIM];
            float mx = -1e30f;
            for (int j = 0; j < V_DIM; j++) {
                l[j] = p.base[i * V_DIM + j] + 0.5f * p.learned[(h * V_DIM + i) * V_DIM + j];
                mx = fmaxf(mx, l[j]);
            }
            float sum = 0.f;
            for (int j = 0; j < V_DIM; j++) { l[j] = expf(l[j] - mx); sum += l[j]; }
            float inv = 1.f / sum;
            for (int j = 0; j < V_DIM; j++) g_topo[h][i * V_DIM + j] = l[j] * inv;
        }
    } else {
        float w = p.sdw[tid];
        float sg = 1.f / (1.f + expf(-w));
        g_decay[tid] = fminf(0.99f, fmaxf(0.01f, sg));
    }
}

// ---------------- K1: transpose + qkv_in ----------------
// block = one (t,b); writes g_xt and g_qt in [c][t][b][v] layout.
__global__ void k_trans(const float* __restrict__ x, const float* __restrict__ alpha) {
    __shared__ float alp[C_DIM];
    int tid = threadIdx.x;
    alp[tid] = alpha[tid];
    __syncthreads();

    int t = blockIdx.x >> 5;
    int b = blockIdx.x & 31;
    const float* xin = x + (size_t)t * PLANE + b * (C_DIM * V_DIM);
    const float* xpr = xin - PLANE;
    int nbase = t * 800 + b * V_DIM;

    for (int idx = tid; idx < C_DIM * V_DIM; idx += 256) {
        int c = idx / V_DIM;
        int v = idx - c * V_DIM;
        float xv = xin[idx];
        float g = (t == 0) ? 0.f : fabsf(xv - xpr[idx]);
        float a = alp[c];
        float q = a * g + (1.f - a) * xv;
        int o = c * NF + nbase + v;
        g_xt[o] = xv;
        g_qt[o] = q;
    }
}

// ---------------- K2/K5: SGEMM 256x51200x256 + fused BN ----------------
// Block tile 128(m) x 128(n), BK=8, 256 threads, thread tile 8m x 8n (4 f32x2).
#define BM 128
#define BN 128
#define BK 8
__global__ void __launch_bounds__(256) k_gemm(int pass) {
    int mt;
    const float* Bmat;
    float* out;
    if (pass == 0) {
        mt = blockIdx.z;
        Bmat = (mt == 2) ? g_xt : g_qt;
        out = (mt == 0) ? g_yq : (mt == 1) ? g_yk : g_yv;
    } else {
        mt = 3;
        Bmat = g_qt;     // attn (reused buffer)
        out = g_yq;
    }
    const float* Amat = g_wt[mt];           // [k][m]
    int m0 = blockIdx.y * BM;
    int n0 = blockIdx.x * BN;

    __shared__ ull As2[2][BK][BM];          // A duplicated as f32x2      16 KB
    __shared__ ull Bs2[2][BK][4][16];       // B interleaved [j][tn]       8 KB

    int tid = threadIdx.x;
    int tm = tid >> 4;          // 0..15
    int tn = tid & 15;          // 0..15
    int sr = tid >> 5;          // staging row 0..7
    int sc = (tid & 31) * 4;    // staging col 0..124

    ull acc[8][4];
#pragma unroll
    for (int i = 0; i < 8; i++)
#pragma unroll
        for (int j = 0; j < 4; j++) acc[i][j] = 0ULL;

    const float* Ap = Amat + sr * C_DIM + m0 + sc;
    const float* Bp = Bmat + (size_t)sr * NF + n0 + sc;
    int jj = (sc & 7) >> 1;     // 0 or 2
    int tnb = sc >> 3;

    // prologue: stage chunk 0
    {
        float4 a4 = *reinterpret_cast<const float4*>(Ap);
        float4 b4 = *reinterpret_cast<const float4*>(Bp);
        float4* ad = reinterpret_cast<float4*>(&As2[0][sr][sc]);
        ad[0] = make_float4(a4.x, a4.x, a4.y, a4.y);
        ad[1] = make_float4(a4.z, a4.z, a4.w, a4.w);
        *reinterpret_cast<float2*>(&Bs2[0][sr][jj][tnb])     = make_float2(b4.x, b4.y);
        *reinterpret_cast<float2*>(&Bs2[0][sr][jj + 1][tnb]) = make_float2(b4.z, b4.w);
    }
    __syncthreads();

    for (int kc = 0; kc < C_DIM / BK; kc++) {
        int buf = kc & 1;
        float4 a4, b4;
        bool more = (kc + 1 < C_DIM / BK);
        if (more) {
            a4 = *reinterpret_cast<const float4*>(Ap + (kc + 1) * BK * C_DIM);
            b4 = *reinterpret_cast<const float4*>(Bp + (size_t)(kc + 1) * BK * NF);
        }
#pragma unroll
        for (int kk = 0; kk < BK; kk++) {
            ull b0 = Bs2[buf][kk][0][tn];
            ull b1 = Bs2[buf][kk][1][tn];
            ull b2 = Bs2[buf][kk][2][tn];
            ull b3 = Bs2[buf][kk][3][tn];
            const ull* arow = &As2[buf][kk][tm * 8];
#pragma unroll
            for (int i = 0; i < 8; i++) {
                ull a = arow[i];
                fma2(acc[i][0], a, b0);
                fma2(acc[i][1], a, b1);
                fma2(acc[i][2], a, b2);
                fma2(acc[i][3], a, b3);
            }
        }
        if (more) {
            float4* ad = reinterpret_cast<float4*>(&As2[buf ^ 1][sr][sc]);
            ad[0] = make_float4(a4.x, a4.x, a4.y, a4.y);
            ad[1] = make_float4(a4.z, a4.z, a4.w, a4.w);
            *reinterpret_cast<float2*>(&Bs2[buf ^ 1][sr][jj][tnb])     = make_float2(b4.x, b4.y);
            *reinterpret_cast<float2*>(&Bs2[buf ^ 1][sr][jj + 1][tnb]) = make_float2(b4.z, b4.w);
        }
        __syncthreads();
    }

    // epilogue: fused BN, store 8x8
#pragma unroll
    for (int i = 0; i < 8; i++) {
        int mo = m0 + tm * 8 + i;
        float sc_ = g_scale[mt][mo], sh = g_shift[mt][mo];
        float* dst = out + (size_t)mo * NF + n0 + tn * 8;
        float2 f0 = unpack2(acc[i][0]);
        float2 f1 = unpack2(acc[i][1]);
        float2 f2 = unpack2(acc[i][2]);
        float2 f3 = unpack2(acc[i][3]);
        float4 o0 = make_float4(f0.x * sc_ + sh, f0.y * sc_ + sh, f1.x * sc_ + sh, f1.y * sc_ + sh);
        float4 o1 = make_float4(f2.x * sc_ + sh, f2.y * sc_ + sh, f3.x * sc_ + sh, f3.y * sc_ + sh);
        reinterpret_cast<float4*>(dst)[0] = o0;
        reinterpret_cast<float4*>(dst)[1] = o1;
    }
}

// ---------------- K3: triple LIF + kv_local (float2, new layout) ----------------
__global__ void k_lif3() {
    int gid = blockIdx.x * 256 + threadIdx.x;
    if (gid >= PLANE / 2) return;
    int e = gid * 2;
    int c = e / 800;
    int nb = e - c * 800;
    int base = c * NF + nb;
    float2 vq = make_float2(0, 0), vk = vq, vv = vq;
    for (int t = 0; t < T_DIM; t++) {
        int off = base + t * 800;
        float2 aq = *reinterpret_cast<const float2*>(g_yq + off);
        float2 ak = *reinterpret_cast<const float2*>(g_yk + off);
        float2 av = *reinterpret_cast<const float2*>(g_yv + off);
        float2 sq, skv;
        float* vqp = &vq.x; float* vkp = &vk.x; float* vvp = &vv.x;
        float* aqp = &aq.x; float* akp = &ak.x; float* avp = &av.x;
        float* sqp = &sq.x; float* skvp = &skv.x;
#pragma unroll
        for (int i = 0; i < 2; i++) {
            float q = vqp[i] + (aqp[i] - vqp[i]) * 0.5f;
            float s = (q >= 1.f) ? 1.f : 0.f;
            vqp[i] = q * (1.f - s);
            sqp[i] = s;
            float k = vkp[i] + (akp[i] - vkp[i]) * 0.5f;
            float sk = (k >= 1.f) ? 1.f : 0.f;
            vkp[i] = k * (1.f - sk);
            float v = vvp[i] + (avp[i] - vvp[i]) * 0.5f;
            float sv = (v >= 1.f) ? 1.f : 0.f;
            vvp[i] = v * (1.f - sv);
            skvp[i] = sk * sv;
        }
        *reinterpret_cast<float2*>(g_qs + off) = sq;
        *reinterpret_cast<float2*>(g_kvl + off) = skv;
    }
}

// ---------------- K4: topo routing + LIF(0.5) + SSRE (new layout) ----------------
__global__ void __launch_bounds__(224) k_topo_ssre() {
    int bid = blockIdx.x;
    int b = bid >> 5;
    int rest = bid & 31;
    int h = rest >> 2;
    int dg = rest & 3;
    int tid = threadIdx.x;

    __shared__ float topo_s[V_DIM * V_DIM];
    __shared__ float kvb[2][200];
    for (int i = tid; i < V_DIM * V_DIM; i += 224) topo_s[i] = g_topo[h][i];

    bool active = tid < 200;
    int d_local = tid / V_DIM;
    int i = tid - d_local * V_DIM;
    int c = h * HD_DIM + dg * 8 + d_local;
    int pbase = c * NF + b * V_DIM + i;   // + t*800 per step

    float dec = 0.f;
    if (active) dec = g_decay[h * HD_DIM + dg * 8 + d_local];
    float omd = 1.f - dec;
    float vm = 0.f, S = 0.f;

    if (active) kvb[0][tid] = g_kvl[pbase];

    for (int t = 0; t < T_DIM; t++) {
        __syncthreads();
        int cur = t & 1;
        if (t + 1 < T_DIM && active) kvb[cur ^ 1][tid] = g_kvl[pbase + (t + 1) * 800];
        if (active) {
            const float* kr = &kvb[cur][d_local * V_DIM];
            const float* tr = &topo_s[i * V_DIM];
            float sp = 0.f, sp2 = 0.f;
#pragma unroll
            for (int j = 0; j < 24; j += 2) {
                sp += tr[j] * kr[j];
                sp2 += tr[j + 1] * kr[j + 1];
            }
            sp += tr[24] * kr[24] + sp2;
            vm = vm + (sp - vm) * 0.5f;
            float sk = (vm >= 0.5f) ? 1.f : 0.f;
            vm *= (1.f - sk);
            S = dec * S + omd * sk;
            int off = pbase + t * 800;
            g_qt[off] = g_qs[off] * S;    // attn (reuses qkv_in buffer)
        }
    }
}

// ---------------- K6: final LIF(0.5) + identity ----------------
__global__ void k_final(const float* __restrict__ x, float* __restrict__ out) {
    int e = blockIdx.x * 256 + threadIdx.x;
    if (e >= PLANE) return;
    int c = e / 800;
    int nb = e - c * 800;
    int b = nb / V_DIM;
    int v = nb - b * V_DIM;
    int ybase = c * NF + nb;                          // yproj layout
    int xoff = b * (C_DIM * V_DIM) + c * V_DIM + v;   // original layout
    float vm = 0.f;
    for (int t = 0; t < T_DIM; t++) {
        float y = g_yq[ybase + t * 800];
        float vv = vm + (y - vm) * 0.5f;
        float s = (vv >= 0.5f) ? 1.f : 0.f;
        vm = vv * (1.f - s);
        int xo = t * PLANE + xoff;
        out[xo] = s + x[xo];
    }
}

// ---------------- launch ----------------
extern "C" void kernel_launch(void* const* d_in, const int* in_sizes, int n_in,
                              void* d_out, int out_size) {
    const float* x = (const float*)d_in[0];
    const float* alpha = (const float*)d_in[1];

    PrepArgs p;
    p.w[0] = (const float*)d_in[2];
    p.w[1] = (const float*)d_in[3];
    p.w[2] = (const float*)d_in[4];

    if (in_sizes[5] == 625) {
        p.base    = (const float*)d_in[5];
        p.learned = (const float*)d_in[6];
        p.sdw     = (const float*)d_in[7];
        p.w[3]    = (const float*)d_in[8];
        p.projb   = (const float*)d_in[9];
        for (int m = 0; m < 4; m++) {
            int o = 10 + m * 4;
            p.gamma[m] = (const float*)d_in[o + 0];
            p.beta[m]  = (const float*)d_in[o + 1];
            p.mean[m]  = (const float*)d_in[o + 2];
            p.var[m]   = (const float*)d_in[o + 3];
        }
    } else {
        for (int m = 0; m < 3; m++) {
            int o = 5 + m * 4;
            p.gamma[m] = (const float*)d_in[o + 0];
            p.beta[m]  = (const float*)d_in[o + 1];
            p.mean[m]  = (const float*)d_in[o + 2];
            p.var[m]   = (const float*)d_in[o + 3];
        }
        p.base    = (const float*)d_in[17];
        p.learned = (const float*)d_in[18];
        p.sdw     = (const float*)d_in[19];
        p.w[3]    = (const float*)d_in[20];
        p.projb   = (const float*)d_in[21];
        p.gamma[3] = (const float*)d_in[22];
        p.beta[3]  = (const float*)d_in[23];
        p.mean[3]  = (const float*)d_in[24];
        p.var[3]   = (const float*)d_in[25];
    }

    float* out = (float*)d_out;

    k_prep<<<6, 256>>>(p);
    k_trans<<<T_DIM * B_DIM, 256>>>(x, alpha);
    k_gemm<<<dim3(NF / BN, C_DIM / BM, 3), 256>>>(0);
    k_lif3<<<(PLANE / 2 + 255) / 256, 256>>>();
    k_topo_ssre<<<B_DIM * H_DIM * 4, 224>>>();
    k_gemm<<<dim3(NF / BN, C_DIM / BM, 1), 256>>>(1);
    k_final<<<(PLANE + 255) / 256, 256>>>(x, out);
}

// round 7
// speedup vs baseline: 1.4568x; 1.1603x over previous
#include <cuda_runtime.h>
#include <math.h>
#include <stdint.h>

typedef unsigned long long ull;

// ---------------- problem constants ----------------
#define T_DIM 64
#define B_DIM 32
#define C_DIM 256
#define V_DIM 25
#define H_DIM 8
#define HD_DIM 32
#define PLANE  (B_DIM * C_DIM * V_DIM)    // 204800
#define TOT    (T_DIM * PLANE)            // 13107200
#define NF     (T_DIM * B_DIM * V_DIM)    // 51200  (GEMM N)

// ---------------- device scratch ----------------
// GEMM-adjacent layout: [c][t][b][v]  (addr = c*NF + t*800 + b*25 + v)
__device__ __align__(16) float g_xt[TOT];    // x transposed
__device__ __align__(16) float g_qt[TOT];    // qkv_in transposed; later attn
__device__ __align__(16) float g_yq[TOT];    // q bn-conv out; later proj bn-conv out
__device__ __align__(16) float g_yk[TOT];
__device__ __align__(16) float g_yv[TOT];
__device__ __align__(16) float g_qs[TOT];    // q spikes
__device__ __align__(16) float g_kvl[TOT];   // k_s * v_s

__device__ float g_scale[4][C_DIM];
__device__ float g_shift[4][C_DIM];
__device__ float g_topo[H_DIM][V_DIM * V_DIM];
__device__ float g_decay[C_DIM];

// ---------------- helpers ----------------
__device__ __forceinline__ void split_tf32(float x, uint32_t& h, uint32_t& l) {
    asm("cvt.rna.tf32.f32 %0, %1;" : "=r"(h) : "f"(x));
    float lf = x - __uint_as_float(h);
    asm("cvt.rna.tf32.f32 %0, %1;" : "=r"(l) : "f"(lf));
}
// m16n8k8 tf32 mma: acc (4 f32) += A(4 tf32) x B(2 tf32)
__device__ __forceinline__ void mma8(float* c, float4 a, float2 b) {
    asm volatile(
        "mma.sync.aligned.m16n8k8.row.col.f32.tf32.tf32.f32 "
        "{%0,%1,%2,%3}, {%4,%5,%6,%7}, {%8,%9}, {%0,%1,%2,%3};"
        : "+f"(c[0]), "+f"(c[1]), "+f"(c[2]), "+f"(c[3])
        : "r"(__float_as_uint(a.x)), "r"(__float_as_uint(a.y)),
          "r"(__float_as_uint(a.z)), "r"(__float_as_uint(a.w)),
          "r"(__float_as_uint(b.x)), "r"(__float_as_uint(b.y)));
}

// ---------------- K0: prep ----------------
struct PrepArgs {
    const float* w[4];
    const float* gamma[4];
    const float* beta[4];
    const float* mean[4];
    const float* var[4];
    const float* projb;
    const float* base;
    const float* learned;
    const float* sdw;
};

__global__ void k_prep(PrepArgs p) {
    int blk = blockIdx.x, tid = threadIdx.x;
    if (blk < 4) {
        float sc = p.gamma[blk][tid] * rsqrtf(p.var[blk][tid] + 1e-5f);
        float sh = p.beta[blk][tid] - p.mean[blk][tid] * sc;
        if (blk == 3) sh += p.projb[tid] * sc;
        g_scale[blk][tid] = sc;
        g_shift[blk][tid] = sh;
    } else if (blk == 4) {
        if (tid < H_DIM * V_DIM) {
            int h = tid / V_DIM, i = tid - h * V_DIM;
            float l[V_DIM];
            float mx = -1e30f;
            for (int j = 0; j < V_DIM; j++) {
                l[j] = p.base[i * V_DIM + j] + 0.5f * p.learned[(h * V_DIM + i) * V_DIM + j];
                mx = fmaxf(mx, l[j]);
            }
            float sum = 0.f;
            for (int j = 0; j < V_DIM; j++) { l[j] = expf(l[j] - mx); sum += l[j]; }
            float inv = 1.f / sum;
            for (int j = 0; j < V_DIM; j++) g_topo[h][i * V_DIM + j] = l[j] * inv;
        }
    } else {
        float w = p.sdw[tid];
        float sg = 1.f / (1.f + expf(-w));
        g_decay[tid] = fminf(0.99f, fmaxf(0.01f, sg));
    }
}

// ---------------- K1: transpose + qkv_in ----------------
__global__ void k_trans(const float* __restrict__ x, const float* __restrict__ alpha) {
    __shared__ float alp[C_DIM];
    int tid = threadIdx.x;
    alp[tid] = alpha[tid];
    __syncthreads();

    int t = blockIdx.x >> 5;
    int b = blockIdx.x & 31;
    const float* xin = x + (size_t)t * PLANE + b * (C_DIM * V_DIM);
    const float* xpr = xin - PLANE;
    int nbase = t * 800 + b * V_DIM;

    for (int idx = tid; idx < C_DIM * V_DIM; idx += 256) {
        int c = idx / V_DIM;
        int v = idx - c * V_DIM;
        float xv = xin[idx];
        float g = (t == 0) ? 0.f : fabsf(xv - xpr[idx]);
        float a = alp[c];
        float q = a * g + (1.f - a) * xv;
        int o = c * NF + nbase + v;
        g_xt[o] = xv;
        g_qt[o] = q;
    }
}

// ---------------- K2/K5: tf32x3 mma.sync GEMM + fused BN ----------------
// Block tile 128x128, BK=16, 512 threads (16 warps), warp tile 64x16.
// Smem holds fragment-packed tf32 hi/lo tiles, double-buffered.
#define BM 128
#define BN 128
#define BK 16
#define GTHREADS 512
// float offsets inside one buffer (8192 floats = 32 KB)
#define AH_OFF 0
#define AL_OFF 2048
#define BH_OFF 4096
#define BL_OFF 6144
#define BUF_FLOATS 8192
#define GSMEM_BYTES (2 * BUF_FLOATS * 4)

struct GemmArgs { const float* w0; const float* w1; const float* w2; const float* w3; };

__device__ __forceinline__ void stage_load(const float* __restrict__ A, const float* __restrict__ B,
                                           int kc, int m0, int n0, int tid,
                                           float* ra, float* rb) {
    int k0 = kc * BK;
    {   // A: one fragment-lane per thread. frag = rest = kf*8+mf, lane slot.
        int lane = tid & 31, rest = tid >> 5;   // rest 0..15
        int mf = rest & 7, kf = rest >> 3;
        int g = lane >> 2, c = lane & 3;
        const float* ap = A + (size_t)(m0 + mf * 16 + g) * C_DIM + k0 + kf * 8 + c;
        ra[0] = ap[0];
        ra[1] = ap[8 * C_DIM];
        ra[2] = ap[4];
        ra[3] = ap[8 * C_DIM + 4];
    }
#pragma unroll
    for (int i = 0; i < 2; i++) {  // B: two fragment-lanes per thread. frag = rest = kf*16+nf
        int fl = tid + i * GTHREADS;
        int lane = fl & 31, rest = fl >> 5;     // rest 0..31
        int nf = rest & 15, kf = rest >> 4;
        int g = lane >> 2, c = lane & 3;
        const float* bp = B + (size_t)(k0 + kf * 8 + c) * NF + n0 + nf * 8 + g;
        rb[i * 2 + 0] = bp[0];
        rb[i * 2 + 1] = bp[4 * NF];
    }
}

__device__ __forceinline__ void stage_store(float* sb, int tid, const float* ra, const float* rb) {
    {   // A
        int lane = tid & 31, rest = tid >> 5;
        uint32_t h[4], l[4];
#pragma unroll
        for (int j = 0; j < 4; j++) split_tf32(ra[j], h[j], l[j]);
        int fi = (rest * 32 + lane) * 4;
        *reinterpret_cast<float4*>(sb + AH_OFF + fi) =
            make_float4(__uint_as_float(h[0]), __uint_as_float(h[1]),
                        __uint_as_float(h[2]), __uint_as_float(h[3]));
        *reinterpret_cast<float4*>(sb + AL_OFF + fi) =
            make_float4(__uint_as_float(l[0]), __uint_as_float(l[1]),
                        __uint_as_float(l[2]), __uint_as_float(l[3]));
    }
#pragma unroll
    for (int i = 0; i < 2; i++) {   // B
        int fl = tid + i * GTHREADS;
        int lane = fl & 31, rest = fl >> 5;
        uint32_t h0, l0, h1, l1;
        split_tf32(rb[i * 2 + 0], h0, l0);
        split_tf32(rb[i * 2 + 1], h1, l1);
        int fi = (rest * 32 + lane) * 2;
        *reinterpret_cast<float2*>(sb + BH_OFF + fi) =
            make_float2(__uint_as_float(h0), __uint_as_float(h1));
        *reinterpret_cast<float2*>(sb + BL_OFF + fi) =
            make_float2(__uint_as_float(l0), __uint_as_float(l1));
    }
}

__global__ void __launch_bounds__(GTHREADS, 1) k_gemm_mma(GemmArgs ga, int pass) {
    extern __shared__ float sm[];
    int mt;
    const float* A;
    const float* B;
    float* out;
    if (pass == 0) {
        mt = blockIdx.z;
        A = (mt == 0) ? ga.w0 : (mt == 1) ? ga.w1 : ga.w2;
        B = (mt == 2) ? g_xt : g_qt;
        out = (mt == 0) ? g_yq : (mt == 1) ? g_yk : g_yv;
    } else {
        mt = 3;
        A = ga.w3;
        B = g_qt;
        out = g_yq;
    }
    int m0 = blockIdx.y * BM;
    int n0 = blockIdx.x * BN;
    int tid = threadIdx.x;
    int lane = tid & 31, wid = tid >> 5;
    int wm = wid >> 3;   // 0..1  -> 64 rows
    int wn = wid & 7;    // 0..7  -> 16 cols (2 nf)

    float acc[4][2][4];
#pragma unroll
    for (int i = 0; i < 4; i++)
#pragma unroll
        for (int j = 0; j < 2; j++)
#pragma unroll
            for (int r = 0; r < 4; r++) acc[i][j][r] = 0.f;

    float ra[4], rb[4];
    stage_load(A, B, 0, m0, n0, tid, ra, rb);
    stage_store(sm, tid, ra, rb);
    __syncthreads();

    for (int kc = 0; kc < C_DIM / BK; kc++) {
        float* sb = sm + (kc & 1) * BUF_FLOATS;
        bool more = (kc + 1 < C_DIM / BK);
        if (more) stage_load(A, B, kc + 1, m0, n0, tid, ra, rb);

#pragma unroll
        for (int kf = 0; kf < 2; kf++) {
            float4 Ah4[4], Al4[4];
#pragma unroll
            for (int i = 0; i < 4; i++) {
                int fi = ((kf * 8 + wm * 4 + i) * 32 + lane) * 4;
                Ah4[i] = *reinterpret_cast<const float4*>(sb + AH_OFF + fi);
                Al4[i] = *reinterpret_cast<const float4*>(sb + AL_OFF + fi);
            }
            float2 Bh2[2], Bl2[2];
#pragma unroll
            for (int j = 0; j < 2; j++) {
                int fi = ((kf * 16 + wn * 2 + j) * 32 + lane) * 2;
                Bh2[j] = *reinterpret_cast<const float2*>(sb + BH_OFF + fi);
                Bl2[j] = *reinterpret_cast<const float2*>(sb + BL_OFF + fi);
            }
#pragma unroll
            for (int i = 0; i < 4; i++)
#pragma unroll
                for (int j = 0; j < 2; j++) {
                    mma8(acc[i][j], Ah4[i], Bh2[j]);
                    mma8(acc[i][j], Ah4[i], Bl2[j]);
                    mma8(acc[i][j], Al4[i], Bh2[j]);
                }
        }
        if (more) stage_store(sm + ((kc + 1) & 1) * BUF_FLOATS, tid, ra, rb);
        __syncthreads();
    }

    // epilogue: fused BN, direct fragment stores
    int g = lane >> 2, c = lane & 3;
#pragma unroll
    for (int i = 0; i < 4; i++) {
        int r0 = m0 + wm * 64 + i * 16 + g;
        int r1 = r0 + 8;
        float sc0 = g_scale[mt][r0], sh0 = g_shift[mt][r0];
        float sc1 = g_scale[mt][r1], sh1 = g_shift[mt][r1];
#pragma unroll
        for (int j = 0; j < 2; j++) {
            int ncol = n0 + (wn * 2 + j) * 8 + c * 2;
            *reinterpret_cast<float2*>(out + (size_t)r0 * NF + ncol) =
                make_float2(acc[i][j][0] * sc0 + sh0, acc[i][j][1] * sc0 + sh0);
            *reinterpret_cast<float2*>(out + (size_t)r1 * NF + ncol) =
                make_float2(acc[i][j][2] * sc1 + sh1, acc[i][j][3] * sc1 + sh1);
        }
    }
}

// ---------------- K3: triple LIF + kv_local ----------------
__global__ void k_lif3() {
    int e = blockIdx.x * 256 + threadIdx.x;
    if (e >= PLANE) return;
    int c = e / 800;
    int nb = e - c * 800;
    int bse = c * NF + nb;
    float vq = 0.f, vk = 0.f, vv = 0.f;
    for (int t = 0; t < T_DIM; t++) {
        int off = bse + t * 800;
        float aq = __ldcs(g_yq + off);
        float ak = __ldcs(g_yk + off);
        float av = __ldcs(g_yv + off);
        float q = vq + (aq - vq) * 0.5f;
        float sq = (q >= 1.f) ? 1.f : 0.f;
        vq = q * (1.f - sq);
        float k = vk + (ak - vk) * 0.5f;
        float sk = (k >= 1.f) ? 1.f : 0.f;
        vk = k * (1.f - sk);
        float v = vv + (av - vv) * 0.5f;
        float sv = (v >= 1.f) ? 1.f : 0.f;
        vv = v * (1.f - sv);
        g_qs[off] = sq;
        g_kvl[off] = sk * sv;
    }
}

// ---------------- K4: topo routing + LIF(0.5) + SSRE ----------------
__global__ void __launch_bounds__(224) k_topo_ssre() {
    int bid = blockIdx.x;
    int b = bid >> 5;
    int rest = bid & 31;
    int h = rest >> 2;
    int dg = rest & 3;
    int tid = threadIdx.x;

    __shared__ float topo_s[V_DIM * V_DIM];
    __shared__ float kvb[2][200];
    for (int i = tid; i < V_DIM * V_DIM; i += 224) topo_s[i] = g_topo[h][i];

    bool active = tid < 200;
    int d_local = tid / V_DIM;
    int i = tid - d_local * V_DIM;
    int c = h * HD_DIM + dg * 8 + d_local;
    int pbase = c * NF + b * V_DIM + i;

    float dec = 0.f;
    if (active) dec = g_decay[h * HD_DIM + dg * 8 + d_local];
    float omd = 1.f - dec;
    float vm = 0.f, S = 0.f;

    if (active) kvb[0][tid] = g_kvl[pbase];

    for (int t = 0; t < T_DIM; t++) {
        __syncthreads();
        int cur = t & 1;
        if (t + 1 < T_DIM && active) kvb[cur ^ 1][tid] = g_kvl[pbase + (t + 1) * 800];
        if (active) {
            const float* kr = &kvb[cur][d_local * V_DIM];
            const float* tr = &topo_s[i * V_DIM];
            float sp = 0.f, sp2 = 0.f;
#pragma unroll
            for (int j = 0; j < 24; j += 2) {
                sp += tr[j] * kr[j];
                sp2 += tr[j + 1] * kr[j + 1];
            }
            sp += tr[24] * kr[24] + sp2;
            vm = vm + (sp - vm) * 0.5f;
            float sk = (vm >= 0.5f) ? 1.f : 0.f;
            vm *= (1.f - sk);
            S = dec * S + omd * sk;
            int off = pbase + t * 800;
            g_qt[off] = g_qs[off] * S;
        }
    }
}

// ---------------- K6: final LIF(0.5) + identity ----------------
__global__ void k_final(const float* __restrict__ x, float* __restrict__ out) {
    int e = blockIdx.x * 256 + threadIdx.x;
    if (e >= PLANE) return;
    int c = e / 800;
    int nb = e - c * 800;
    int b = nb / V_DIM;
    int v = nb - b * V_DIM;
    int ybase = c * NF + nb;
    int xoff = b * (C_DIM * V_DIM) + c * V_DIM + v;
    float vm = 0.f;
    for (int t = 0; t < T_DIM; t++) {
        float y = __ldcs(g_yq + ybase + t * 800);
        float vv = vm + (y - vm) * 0.5f;
        float s = (vv >= 0.5f) ? 1.f : 0.f;
        vm = vv * (1.f - s);
        int xo = t * PLANE + xoff;
        out[xo] = s + x[xo];
    }
}

// ---------------- launch ----------------
extern "C" void kernel_launch(void* const* d_in, const int* in_sizes, int n_in,
                              void* d_out, int out_size) {
    const float* x = (const float*)d_in[0];
    const float* alpha = (const float*)d_in[1];

    PrepArgs p;
    p.w[0] = (const float*)d_in[2];
    p.w[1] = (const float*)d_in[3];
    p.w[2] = (const float*)d_in[4];

    if (in_sizes[5] == 625) {
        p.base    = (const float*)d_in[5];
        p.learned = (const float*)d_in[6];
        p.sdw     = (const float*)d_in[7];
        p.w[3]    = (const float*)d_in[8];
        p.projb   = (const float*)d_in[9];
        for (int m = 0; m < 4; m++) {
            int o = 10 + m * 4;
            p.gamma[m] = (const float*)d_in[o + 0];
            p.beta[m]  = (const float*)d_in[o + 1];
            p.mean[m]  = (const float*)d_in[o + 2];
            p.var[m]   = (const float*)d_in[o + 3];
        }
    } else {
        for (int m = 0; m < 3; m++) {
            int o = 5 + m * 4;
            p.gamma[m] = (const float*)d_in[o + 0];
            p.beta[m]  = (const float*)d_in[o + 1];
            p.mean[m]  = (const float*)d_in[o + 2];
            p.var[m]   = (const float*)d_in[o + 3];
        }
        p.base    = (const float*)d_in[17];
        p.learned = (const float*)d_in[18];
        p.sdw     = (const float*)d_in[19];
        p.w[3]    = (const float*)d_in[20];
        p.projb   = (const float*)d_in[21];
        p.gamma[3] = (const float*)d_in[22];
        p.beta[3]  = (const float*)d_in[23];
        p.mean[3]  = (const float*)d_in[24];
        p.var[3]   = (const float*)d_in[25];
    }

    float* out = (float*)d_out;

    cudaFuncSetAttribute(k_gemm_mma, cudaFuncAttributeMaxDynamicSharedMemorySize, GSMEM_BYTES);

    GemmArgs ga;
    ga.w0 = p.w[0]; ga.w1 = p.w[1]; ga.w2 = p.w[2]; ga.w3 = p.w[3];

    k_prep<<<6, 256>>>(p);
    k_trans<<<T_DIM * B_DIM, 256>>>(x, alpha);
    k_gemm_mma<<<dim3(NF / BN, C_DIM / BM, 3), GTHREADS, GSMEM_BYTES>>>(ga, 0);
    k_lif3<<<(PLANE + 255) / 256, 256>>>();
    k_topo_ssre<<<B_DIM * H_DIM * 4, 224>>>();
    k_gemm_mma<<<dim3(NF / BN, C_DIM / BM, 1), GTHREADS, GSMEM_BYTES>>>(ga, 1);
    k_final<<<(PLANE + 255) / 256, 256>>>(x, out);
}